// round 2
// baseline (speedup 1.0000x reference)
#include <cuda_runtime.h>
#include <math.h>

#define TMAX   8192
#define DDIM   1024
#define HDIM   4096
#define ENUM   8
#define KTOP   2

// ---------------- device scratch (static; no allocations allowed) ----------
__device__ int   g_count[ENUM];
__device__ int   g_offset[ENUM];
__device__ int   g_tok[ENUM * TMAX];
__device__ float g_wgt[ENUM * TMAX];
// H activations for all T*K assignments: 16384 x 4096 fp32 = 268 MB
__device__ float g_hbuf[(size_t)TMAX * KTOP * HDIM];

// ---------------- small kernels --------------------------------------------
__global__ void zero_counts_kernel() {
    if (threadIdx.x < ENUM) g_count[threadIdx.x] = 0;
}

__global__ void zero_out_kernel(float4* out, int n4) {
    int i = blockIdx.x * blockDim.x + threadIdx.x;
    int stride = gridDim.x * blockDim.x;
    float4 z = make_float4(0.f, 0.f, 0.f, 0.f);
    for (; i < n4; i += stride) out[i] = z;
}

__global__ void scan_kernel() {
    if (threadIdx.x == 0) {
        int acc = 0;
        for (int e = 0; e < ENUM; e++) { g_offset[e] = acc; acc += g_count[e]; }
    }
}

// ---------------- router: 1 warp per token ---------------------------------
__global__ void router_kernel(const float* __restrict__ x,
                              const float* __restrict__ gate_w, int T) {
    int t = blockIdx.x * (blockDim.x / 32) + (threadIdx.x >> 5);
    int lane = threadIdx.x & 31;
    if (t >= T) return;

    const float* xr = x + (size_t)t * DDIM;
    float acc[ENUM];
#pragma unroll
    for (int e = 0; e < ENUM; e++) acc[e] = 0.f;

    for (int d = lane; d < DDIM; d += 32) {
        float xv = xr[d];
#pragma unroll
        for (int e = 0; e < ENUM; e++) acc[e] += xv * gate_w[e * DDIM + d];
    }
#pragma unroll
    for (int o = 16; o > 0; o >>= 1) {
#pragma unroll
        for (int e = 0; e < ENUM; e++)
            acc[e] += __shfl_xor_sync(0xFFFFFFFFu, acc[e], o);
    }

    if (lane == 0) {
        // softmax over 8 logits
        float m = acc[0];
#pragma unroll
        for (int e = 1; e < ENUM; e++) m = fmaxf(m, acc[e]);
        float p[ENUM], Z = 0.f;
#pragma unroll
        for (int e = 0; e < ENUM; e++) { p[e] = expf(acc[e] - m); Z += p[e]; }
#pragma unroll
        for (int e = 0; e < ENUM; e++) p[e] /= Z;

        // top-2 (strict > keeps lowest index on ties, matching lax.top_k)
        int i1 = 0; float p1 = p[0];
#pragma unroll
        for (int e = 1; e < ENUM; e++) if (p[e] > p1) { p1 = p[e]; i1 = e; }
        int i2 = -1; float p2 = -1.f;
#pragma unroll
        for (int e = 0; e < ENUM; e++)
            if (e != i1 && p[e] > p2) { p2 = p[e]; i2 = e; }

        float inv = 1.f / (p1 + p2 + 1e-9f);
        float w1v = p1 * inv, w2v = p2 * inv;

        int pos1 = atomicAdd(&g_count[i1], 1);
        g_tok[i1 * TMAX + pos1] = t;  g_wgt[i1 * TMAX + pos1] = w1v;
        int pos2 = atomicAdd(&g_count[i2], 1);
        g_tok[i2 * TMAX + pos2] = t;  g_wgt[i2 * TMAX + pos2] = w2v;
    }
}

// ---------------- GEMM1: Hbuf = gelu(gather(X) @ w1[e] + b1[e]) ------------
// tile 64x64, BK=16, 256 threads, 4x4 microtile
__device__ __forceinline__ float gelu_exact(float v) {
    return 0.5f * v * (1.0f + erff(v * 0.70710678118654752f));
}

__global__ void gemm1_kernel(const float* __restrict__ x,
                             const float* __restrict__ w1,
                             const float* __restrict__ b1) {
    const int e = blockIdx.z;
    const int cnt = g_count[e];
    const int row0 = blockIdx.x * 64;
    if (row0 >= cnt) return;
    const int col0 = blockIdx.y * 64;
    const int off = g_offset[e];

    __shared__ float As[16][68];   // [kk][row], padded
    __shared__ float Bs[16][64];   // [kk][col]

    const int tid = threadIdx.y * 16 + threadIdx.x;
    const int tx = threadIdx.x, ty = threadIdx.y;

    // gather token for the row this thread loads (4 rows of A per thread grouping)
    const int a_r  = tid >> 2;          // 0..63
    const int a_k4 = (tid & 3) * 4;     // 0,4,8,12
    int a_tok = -1;
    if (row0 + a_r < cnt) a_tok = g_tok[e * TMAX + row0 + a_r];
    const float* a_src = (a_tok >= 0) ? (x + (size_t)a_tok * DDIM) : nullptr;

    const int b_kk = tid >> 4;          // 0..15
    const int b_c4 = (tid & 15) * 4;    // 0..60
    const float* w1e = w1 + (size_t)e * DDIM * HDIM;

    float c[4][4];
#pragma unroll
    for (int i = 0; i < 4; i++)
#pragma unroll
        for (int j = 0; j < 4; j++) c[i][j] = 0.f;

    for (int k0 = 0; k0 < DDIM; k0 += 16) {
        // load A tile (transposed into As[kk][r])
        float4 av = make_float4(0.f, 0.f, 0.f, 0.f);
        if (a_src) av = *(const float4*)(a_src + k0 + a_k4);
        As[a_k4 + 0][a_r] = av.x;
        As[a_k4 + 1][a_r] = av.y;
        As[a_k4 + 2][a_r] = av.z;
        As[a_k4 + 3][a_r] = av.w;
        // load B tile
        float4 bv = *(const float4*)(w1e + (size_t)(k0 + b_kk) * HDIM + col0 + b_c4);
        *(float4*)&Bs[b_kk][b_c4] = bv;
        __syncthreads();

#pragma unroll
        for (int kk = 0; kk < 16; kk++) {
            float4 a = *(const float4*)&As[kk][ty * 4];
            float4 b = *(const float4*)&Bs[kk][tx * 4];
            c[0][0] += a.x * b.x; c[0][1] += a.x * b.y; c[0][2] += a.x * b.z; c[0][3] += a.x * b.w;
            c[1][0] += a.y * b.x; c[1][1] += a.y * b.y; c[1][2] += a.y * b.z; c[1][3] += a.y * b.w;
            c[2][0] += a.z * b.x; c[2][1] += a.z * b.y; c[2][2] += a.z * b.z; c[2][3] += a.z * b.w;
            c[3][0] += a.w * b.x; c[3][1] += a.w * b.y; c[3][2] += a.w * b.z; c[3][3] += a.w * b.w;
        }
        __syncthreads();
    }

    // epilogue: +b1, gelu, store to Hbuf
    const float* b1e = b1 + (size_t)e * HDIM;
#pragma unroll
    for (int i = 0; i < 4; i++) {
        int r = row0 + ty * 4 + i;
        if (r >= cnt) continue;
        float* dst = g_hbuf + (size_t)(off + r) * HDIM + col0 + tx * 4;
        float4 v;
        v.x = gelu_exact(c[i][0] + b1e[col0 + tx * 4 + 0]);
        v.y = gelu_exact(c[i][1] + b1e[col0 + tx * 4 + 1]);
        v.z = gelu_exact(c[i][2] + b1e[col0 + tx * 4 + 2]);
        v.w = gelu_exact(c[i][3] + b1e[col0 + tx * 4 + 3]);
        *(float4*)dst = v;
    }
}

// ---------------- GEMM2: out[tok] += w * (Hrows @ w2[e] + b2[e]) -----------
__global__ void gemm2_kernel(const float* __restrict__ w2,
                             const float* __restrict__ b2,
                             float* __restrict__ out) {
    const int e = blockIdx.z;
    const int cnt = g_count[e];
    const int row0 = blockIdx.x * 64;
    if (row0 >= cnt) return;
    const int col0 = blockIdx.y * 64;
    const int off = g_offset[e];

    __shared__ float As[16][68];
    __shared__ float Bs[16][64];

    const int tid = threadIdx.y * 16 + threadIdx.x;
    const int tx = threadIdx.x, ty = threadIdx.y;

    const int a_r  = tid >> 2;
    const int a_k4 = (tid & 3) * 4;
    const bool a_ok = (row0 + a_r < cnt);
    const float* a_src = g_hbuf + (size_t)(off + row0 + a_r) * HDIM;

    const int b_kk = tid >> 4;
    const int b_c4 = (tid & 15) * 4;
    const float* w2e = w2 + (size_t)e * HDIM * DDIM;

    float c[4][4];
#pragma unroll
    for (int i = 0; i < 4; i++)
#pragma unroll
        for (int j = 0; j < 4; j++) c[i][j] = 0.f;

    for (int k0 = 0; k0 < HDIM; k0 += 16) {
        float4 av = make_float4(0.f, 0.f, 0.f, 0.f);
        if (a_ok) av = *(const float4*)(a_src + k0 + a_k4);
        As[a_k4 + 0][a_r] = av.x;
        As[a_k4 + 1][a_r] = av.y;
        As[a_k4 + 2][a_r] = av.z;
        As[a_k4 + 3][a_r] = av.w;
        float4 bv = *(const float4*)(w2e + (size_t)(k0 + b_kk) * DDIM + col0 + b_c4);
        *(float4*)&Bs[b_kk][b_c4] = bv;
        __syncthreads();

#pragma unroll
        for (int kk = 0; kk < 16; kk++) {
            float4 a = *(const float4*)&As[kk][ty * 4];
            float4 b = *(const float4*)&Bs[kk][tx * 4];
            c[0][0] += a.x * b.x; c[0][1] += a.x * b.y; c[0][2] += a.x * b.z; c[0][3] += a.x * b.w;
            c[1][0] += a.y * b.x; c[1][1] += a.y * b.y; c[1][2] += a.y * b.z; c[1][3] += a.y * b.w;
            c[2][0] += a.z * b.x; c[2][1] += a.z * b.y; c[2][2] += a.z * b.z; c[2][3] += a.z * b.w;
            c[3][0] += a.w * b.x; c[3][1] += a.w * b.y; c[3][2] += a.w * b.z; c[3][3] += a.w * b.w;
        }
        __syncthreads();
    }

    const float* b2e = b2 + (size_t)e * DDIM;
#pragma unroll
    for (int i = 0; i < 4; i++) {
        int r = row0 + ty * 4 + i;
        if (r >= cnt) continue;
        int tok = g_tok[e * TMAX + r];
        float w = g_wgt[e * TMAX + r];
        float* dst = out + (size_t)tok * DDIM + col0 + tx * 4;
#pragma unroll
        for (int j = 0; j < 4; j++) {
            float y = c[i][j] + b2e[col0 + tx * 4 + j];
            atomicAdd(dst + j, w * y);
        }
    }
}

// ---------------- launch ----------------------------------------------------
extern "C" void kernel_launch(void* const* d_in, const int* in_sizes, int n_in,
                              void* d_out, int out_size) {
    const float* x      = (const float*)d_in[0];
    const float* gate_w = (const float*)d_in[1];
    const float* w1     = (const float*)d_in[2];
    const float* b1     = (const float*)d_in[3];
    const float* w2     = (const float*)d_in[4];
    const float* b2     = (const float*)d_in[5];
    float* out = (float*)d_out;

    const int T = in_sizes[0] / DDIM;   // 8192

    zero_counts_kernel<<<1, 32>>>();
    {
        int n4 = out_size / 4;
        int blocks = (n4 + 255) / 256;
        if (blocks > 4096) blocks = 4096;
        zero_out_kernel<<<blocks, 256>>>((float4*)out, n4);
    }
    {
        int warps_per_block = 8;
        int blocks = (T + warps_per_block - 1) / warps_per_block;
        router_kernel<<<blocks, warps_per_block * 32>>>(x, gate_w, T);
    }
    scan_kernel<<<1, 32>>>();

    {
        dim3 grid((T + 63) / 64, HDIM / 64, ENUM);
        dim3 block(16, 16);
        gemm1_kernel<<<grid, block>>>(x, w1, b1);
    }
    {
        dim3 grid((T + 63) / 64, DDIM / 64, ENUM);
        dim3 block(16, 16);
        gemm2_kernel<<<grid, block>>>(w2, b2, out);
    }
}

// round 3
// speedup vs baseline: 1.0007x; 1.0007x over previous
#include <cuda_runtime.h>
#include <math.h>

#define TMAX   8192
#define DDIM   1024
#define HDIM   4096
#define ENUM   8
#define KTOP   2

// ---------------- device scratch (static; no allocations allowed) ----------
__device__ int   g_count[ENUM];
__device__ int   g_offset[ENUM];
__device__ int   g_tok[ENUM * TMAX];
__device__ float g_wgt[ENUM * TMAX];
// H activations for all T*K assignments: 16384 x 4096 fp32 = 268 MB
__device__ float g_hbuf[(size_t)TMAX * KTOP * HDIM];

// ---------------- small kernels --------------------------------------------
__global__ void zero_counts_kernel() {
    if (threadIdx.x < ENUM) g_count[threadIdx.x] = 0;
}

__global__ void zero_out_kernel(float4* out, int n4) {
    int i = blockIdx.x * blockDim.x + threadIdx.x;
    int stride = gridDim.x * blockDim.x;
    float4 z = make_float4(0.f, 0.f, 0.f, 0.f);
    for (; i < n4; i += stride) out[i] = z;
}

__global__ void scan_kernel() {
    if (threadIdx.x == 0) {
        int acc = 0;
        for (int e = 0; e < ENUM; e++) { g_offset[e] = acc; acc += g_count[e]; }
    }
}

// ---------------- router: 1 warp per token ---------------------------------
__global__ void router_kernel(const float* __restrict__ x,
                              const float* __restrict__ gate_w, int T) {
    int t = blockIdx.x * (blockDim.x / 32) + (threadIdx.x >> 5);
    int lane = threadIdx.x & 31;
    if (t >= T) return;

    const float* xr = x + (size_t)t * DDIM;
    float acc[ENUM];
#pragma unroll
    for (int e = 0; e < ENUM; e++) acc[e] = 0.f;

    for (int d = lane; d < DDIM; d += 32) {
        float xv = xr[d];
#pragma unroll
        for (int e = 0; e < ENUM; e++) acc[e] += xv * gate_w[e * DDIM + d];
    }
#pragma unroll
    for (int o = 16; o > 0; o >>= 1) {
#pragma unroll
        for (int e = 0; e < ENUM; e++)
            acc[e] += __shfl_xor_sync(0xFFFFFFFFu, acc[e], o);
    }

    if (lane == 0) {
        // softmax over 8 logits
        float m = acc[0];
#pragma unroll
        for (int e = 1; e < ENUM; e++) m = fmaxf(m, acc[e]);
        float p[ENUM], Z = 0.f;
#pragma unroll
        for (int e = 0; e < ENUM; e++) { p[e] = expf(acc[e] - m); Z += p[e]; }
#pragma unroll
        for (int e = 0; e < ENUM; e++) p[e] /= Z;

        // top-2 (strict > keeps lowest index on ties, matching lax.top_k)
        int i1 = 0; float p1 = p[0];
#pragma unroll
        for (int e = 1; e < ENUM; e++) if (p[e] > p1) { p1 = p[e]; i1 = e; }
        int i2 = -1; float p2 = -1.f;
#pragma unroll
        for (int e = 0; e < ENUM; e++)
            if (e != i1 && p[e] > p2) { p2 = p[e]; i2 = e; }

        float inv = 1.f / (p1 + p2 + 1e-9f);
        float w1v = p1 * inv, w2v = p2 * inv;

        int pos1 = atomicAdd(&g_count[i1], 1);
        g_tok[i1 * TMAX + pos1] = t;  g_wgt[i1 * TMAX + pos1] = w1v;
        int pos2 = atomicAdd(&g_count[i2], 1);
        g_tok[i2 * TMAX + pos2] = t;  g_wgt[i2 * TMAX + pos2] = w2v;
    }
}

// ---------------- GEMM1: Hbuf = gelu(gather(X) @ w1[e] + b1[e]) ------------
// tile 64x64, BK=16, 256 threads, 4x4 microtile
__device__ __forceinline__ float gelu_exact(float v) {
    return 0.5f * v * (1.0f + erff(v * 0.70710678118654752f));
}

__global__ void gemm1_kernel(const float* __restrict__ x,
                             const float* __restrict__ w1,
                             const float* __restrict__ b1) {
    const int e = blockIdx.z;
    const int cnt = g_count[e];
    const int row0 = blockIdx.x * 64;
    if (row0 >= cnt) return;
    const int col0 = blockIdx.y * 64;
    const int off = g_offset[e];

    __shared__ float As[16][68];   // [kk][row], padded
    __shared__ float Bs[16][64];   // [kk][col]

    const int tid = threadIdx.y * 16 + threadIdx.x;
    const int tx = threadIdx.x, ty = threadIdx.y;

    // gather token for the row this thread loads (4 rows of A per thread grouping)
    const int a_r  = tid >> 2;          // 0..63
    const int a_k4 = (tid & 3) * 4;     // 0,4,8,12
    int a_tok = -1;
    if (row0 + a_r < cnt) a_tok = g_tok[e * TMAX + row0 + a_r];
    const float* a_src = (a_tok >= 0) ? (x + (size_t)a_tok * DDIM) : nullptr;

    const int b_kk = tid >> 4;          // 0..15
    const int b_c4 = (tid & 15) * 4;    // 0..60
    const float* w1e = w1 + (size_t)e * DDIM * HDIM;

    float c[4][4];
#pragma unroll
    for (int i = 0; i < 4; i++)
#pragma unroll
        for (int j = 0; j < 4; j++) c[i][j] = 0.f;

    for (int k0 = 0; k0 < DDIM; k0 += 16) {
        // load A tile (transposed into As[kk][r])
        float4 av = make_float4(0.f, 0.f, 0.f, 0.f);
        if (a_src) av = *(const float4*)(a_src + k0 + a_k4);
        As[a_k4 + 0][a_r] = av.x;
        As[a_k4 + 1][a_r] = av.y;
        As[a_k4 + 2][a_r] = av.z;
        As[a_k4 + 3][a_r] = av.w;
        // load B tile
        float4 bv = *(const float4*)(w1e + (size_t)(k0 + b_kk) * HDIM + col0 + b_c4);
        *(float4*)&Bs[b_kk][b_c4] = bv;
        __syncthreads();

#pragma unroll
        for (int kk = 0; kk < 16; kk++) {
            float4 a = *(const float4*)&As[kk][ty * 4];
            float4 b = *(const float4*)&Bs[kk][tx * 4];
            c[0][0] += a.x * b.x; c[0][1] += a.x * b.y; c[0][2] += a.x * b.z; c[0][3] += a.x * b.w;
            c[1][0] += a.y * b.x; c[1][1] += a.y * b.y; c[1][2] += a.y * b.z; c[1][3] += a.y * b.w;
            c[2][0] += a.z * b.x; c[2][1] += a.z * b.y; c[2][2] += a.z * b.z; c[2][3] += a.z * b.w;
            c[3][0] += a.w * b.x; c[3][1] += a.w * b.y; c[3][2] += a.w * b.z; c[3][3] += a.w * b.w;
        }
        __syncthreads();
    }

    // epilogue: +b1, gelu, store to Hbuf
    const float* b1e = b1 + (size_t)e * HDIM;
#pragma unroll
    for (int i = 0; i < 4; i++) {
        int r = row0 + ty * 4 + i;
        if (r >= cnt) continue;
        float* dst = g_hbuf + (size_t)(off + r) * HDIM + col0 + tx * 4;
        float4 v;
        v.x = gelu_exact(c[i][0] + b1e[col0 + tx * 4 + 0]);
        v.y = gelu_exact(c[i][1] + b1e[col0 + tx * 4 + 1]);
        v.z = gelu_exact(c[i][2] + b1e[col0 + tx * 4 + 2]);
        v.w = gelu_exact(c[i][3] + b1e[col0 + tx * 4 + 3]);
        *(float4*)dst = v;
    }
}

// ---------------- GEMM2: out[tok] += w * (Hrows @ w2[e] + b2[e]) -----------
__global__ void gemm2_kernel(const float* __restrict__ w2,
                             const float* __restrict__ b2,
                             float* __restrict__ out) {
    const int e = blockIdx.z;
    const int cnt = g_count[e];
    const int row0 = blockIdx.x * 64;
    if (row0 >= cnt) return;
    const int col0 = blockIdx.y * 64;
    const int off = g_offset[e];

    __shared__ float As[16][68];
    __shared__ float Bs[16][64];

    const int tid = threadIdx.y * 16 + threadIdx.x;
    const int tx = threadIdx.x, ty = threadIdx.y;

    const int a_r  = tid >> 2;
    const int a_k4 = (tid & 3) * 4;
    const bool a_ok = (row0 + a_r < cnt);
    const float* a_src = g_hbuf + (size_t)(off + row0 + a_r) * HDIM;

    const int b_kk = tid >> 4;
    const int b_c4 = (tid & 15) * 4;
    const float* w2e = w2 + (size_t)e * HDIM * DDIM;

    float c[4][4];
#pragma unroll
    for (int i = 0; i < 4; i++)
#pragma unroll
        for (int j = 0; j < 4; j++) c[i][j] = 0.f;

    for (int k0 = 0; k0 < HDIM; k0 += 16) {
        float4 av = make_float4(0.f, 0.f, 0.f, 0.f);
        if (a_ok) av = *(const float4*)(a_src + k0 + a_k4);
        As[a_k4 + 0][a_r] = av.x;
        As[a_k4 + 1][a_r] = av.y;
        As[a_k4 + 2][a_r] = av.z;
        As[a_k4 + 3][a_r] = av.w;
        float4 bv = *(const float4*)(w2e + (size_t)(k0 + b_kk) * DDIM + col0 + b_c4);
        *(float4*)&Bs[b_kk][b_c4] = bv;
        __syncthreads();

#pragma unroll
        for (int kk = 0; kk < 16; kk++) {
            float4 a = *(const float4*)&As[kk][ty * 4];
            float4 b = *(const float4*)&Bs[kk][tx * 4];
            c[0][0] += a.x * b.x; c[0][1] += a.x * b.y; c[0][2] += a.x * b.z; c[0][3] += a.x * b.w;
            c[1][0] += a.y * b.x; c[1][1] += a.y * b.y; c[1][2] += a.y * b.z; c[1][3] += a.y * b.w;
            c[2][0] += a.z * b.x; c[2][1] += a.z * b.y; c[2][2] += a.z * b.z; c[2][3] += a.z * b.w;
            c[3][0] += a.w * b.x; c[3][1] += a.w * b.y; c[3][2] += a.w * b.z; c[3][3] += a.w * b.w;
        }
        __syncthreads();
    }

    const float* b2e = b2 + (size_t)e * DDIM;
#pragma unroll
    for (int i = 0; i < 4; i++) {
        int r = row0 + ty * 4 + i;
        if (r >= cnt) continue;
        int tok = g_tok[e * TMAX + r];
        float w = g_wgt[e * TMAX + r];
        float* dst = out + (size_t)tok * DDIM + col0 + tx * 4;
#pragma unroll
        for (int j = 0; j < 4; j++) {
            float y = c[i][j] + b2e[col0 + tx * 4 + j];
            atomicAdd(dst + j, w * y);
        }
    }
}

// ---------------- launch ----------------------------------------------------
extern "C" void kernel_launch(void* const* d_in, const int* in_sizes, int n_in,
                              void* d_out, int out_size) {
    const float* x      = (const float*)d_in[0];
    const float* gate_w = (const float*)d_in[1];
    const float* w1     = (const float*)d_in[2];
    const float* b1     = (const float*)d_in[3];
    const float* w2     = (const float*)d_in[4];
    const float* b2     = (const float*)d_in[5];
    float* out = (float*)d_out;

    const int T = in_sizes[0] / DDIM;   // 8192

    zero_counts_kernel<<<1, 32>>>();
    {
        int n4 = out_size / 4;
        int blocks = (n4 + 255) / 256;
        if (blocks > 4096) blocks = 4096;
        zero_out_kernel<<<blocks, 256>>>((float4*)out, n4);
    }
    {
        int warps_per_block = 8;
        int blocks = (T + warps_per_block - 1) / warps_per_block;
        router_kernel<<<blocks, warps_per_block * 32>>>(x, gate_w, T);
    }
    scan_kernel<<<1, 32>>>();

    {
        dim3 grid((T + 63) / 64, HDIM / 64, ENUM);
        dim3 block(16, 16);
        gemm1_kernel<<<grid, block>>>(x, w1, b1);
    }
    {
        dim3 grid((T + 63) / 64, DDIM / 64, ENUM);
        dim3 block(16, 16);
        gemm2_kernel<<<grid, block>>>(w2, b2, out);
    }
}

// round 7
// speedup vs baseline: 2.7607x; 2.7589x over previous
#include <cuda_runtime.h>
#include <math.h>

#define DDIM 1024
#define HDIM 4096
#define ENUM 8
#define TMAX 8192
#define NSP  17408

#define BM 128
#define BN 64
#define BK 16
#define STG 3
#define ASTR 20   // A smem row stride (floats): conflict-free, 80B multiple of 16
#define BSTR 72   // B smem k-row stride (floats): conflict-free, 288B multiple of 16

typedef unsigned int u32;

__device__ int   g_count[ENUM];
__device__ int   g_cntp[ENUM];
__device__ int   g_offset[ENUM];
__device__ int   g_total;
__device__ int   g_tok[ENUM * TMAX];
__device__ float g_wgt[ENUM * TMAX];
__device__ u32   g_as_ep[2 * TMAX];

__device__ float g_xbuf[(size_t)NSP * DDIM];
__device__ float g_hbuf[(size_t)NSP * HDIM];
__device__ float g_ybuf[(size_t)NSP * DDIM];

// ---------------- helpers ----------------
__device__ __forceinline__ u32 smem_u32(const void* p) {
    u32 a;
    asm("{ .reg .u64 t; cvta.to.shared.u64 t, %1; cvt.u32.u64 %0, t; }" : "=r"(a) : "l"(p));
    return a;
}
__device__ __forceinline__ void cpasync16(u32 dst, const float* src) {
    asm volatile("cp.async.cg.shared.global [%0], [%1], 16;" :: "r"(dst), "l"(src) : "memory");
}
__device__ __forceinline__ u32 f2tf(float x) {
    u32 r;
    asm("cvt.rna.tf32.f32 %0, %1;" : "=r"(r) : "f"(x));
    return r;
}
__device__ __forceinline__ void mmaop(float* c, const u32* a, const u32* b) {
    asm volatile(
        "mma.sync.aligned.m16n8k8.row.col.f32.tf32.tf32.f32 "
        "{%0,%1,%2,%3}, {%4,%5,%6,%7}, {%8,%9}, {%0,%1,%2,%3};"
        : "+f"(c[0]), "+f"(c[1]), "+f"(c[2]), "+f"(c[3])
        : "r"(a[0]), "r"(a[1]), "r"(a[2]), "r"(a[3]), "r"(b[0]), "r"(b[1]));
}
__device__ __forceinline__ float gelu_exact(float v) {
    return 0.5f * v * (1.0f + erff(v * 0.70710678118654752f));
}

// ---------------- support kernels ----------------
__global__ void zero_counts_kernel() {
    if (threadIdx.x < ENUM) g_count[threadIdx.x] = 0;
}

__global__ void router_kernel(const float* __restrict__ x,
                              const float* __restrict__ gate_w, int T) {
    int t = blockIdx.x * (blockDim.x / 32) + (threadIdx.x >> 5);
    int lane = threadIdx.x & 31;
    if (t >= T) return;
    const float* xr = x + (size_t)t * DDIM;
    float acc[ENUM];
#pragma unroll
    for (int e = 0; e < ENUM; e++) acc[e] = 0.f;
    for (int d = lane; d < DDIM; d += 32) {
        float xv = xr[d];
#pragma unroll
        for (int e = 0; e < ENUM; e++) acc[e] += xv * gate_w[e * DDIM + d];
    }
#pragma unroll
    for (int o = 16; o > 0; o >>= 1)
#pragma unroll
        for (int e = 0; e < ENUM; e++)
            acc[e] += __shfl_xor_sync(0xFFFFFFFFu, acc[e], o);
    if (lane == 0) {
        float m = acc[0];
#pragma unroll
        for (int e = 1; e < ENUM; e++) m = fmaxf(m, acc[e]);
        float p[ENUM], Z = 0.f;
#pragma unroll
        for (int e = 0; e < ENUM; e++) { p[e] = expf(acc[e] - m); Z += p[e]; }
#pragma unroll
        for (int e = 0; e < ENUM; e++) p[e] /= Z;
        int i1 = 0; float p1 = p[0];
#pragma unroll
        for (int e = 1; e < ENUM; e++) if (p[e] > p1) { p1 = p[e]; i1 = e; }
        int i2 = -1; float p2 = -1.f;
#pragma unroll
        for (int e = 0; e < ENUM; e++)
            if (e != i1 && p[e] > p2) { p2 = p[e]; i2 = e; }
        float inv = 1.f / (p1 + p2 + 1e-9f);
        int pos1 = atomicAdd(&g_count[i1], 1);
        g_tok[i1 * TMAX + pos1] = t;  g_wgt[i1 * TMAX + pos1] = p1 * inv;
        g_as_ep[2 * t + 0] = ((u32)i1 << 16) | (u32)pos1;
        int pos2 = atomicAdd(&g_count[i2], 1);
        g_tok[i2 * TMAX + pos2] = t;  g_wgt[i2 * TMAX + pos2] = p2 * inv;
        g_as_ep[2 * t + 1] = ((u32)i2 << 16) | (u32)pos2;
    }
}

__global__ void setup_kernel() {
    if (threadIdx.x == 0) {
        int acc = 0;
        for (int e = 0; e < ENUM; e++) {
            g_offset[e] = acc;
            int cp = (g_count[e] + 127) & ~127;
            g_cntp[e] = cp;
            acc += cp;
        }
        g_total = acc;
    }
}

__global__ void gather_kernel(const float* __restrict__ x) {
    int r = blockIdx.x;
    if (r >= g_total) return;
    int e = 0;
#pragma unroll
    for (int i = 1; i < ENUM; i++) if (r >= g_offset[i]) e = i;
    int local = r - g_offset[e];
    float4* dst = (float4*)(g_xbuf + (size_t)r * DDIM);
    if (local < g_count[e]) {
        const float4* src = (const float4*)(x + (size_t)g_tok[e * TMAX + local] * DDIM);
        dst[threadIdx.x] = src[threadIdx.x];
    } else {
        dst[threadIdx.x] = make_float4(0.f, 0.f, 0.f, 0.f);
    }
}

__global__ void combine_kernel(float* __restrict__ out) {
    int t = blockIdx.x;
    u32 e0 = g_as_ep[2 * t], e1 = g_as_ep[2 * t + 1];
    long r0 = (long)g_offset[e0 >> 16] + (e0 & 0xFFFF);
    long r1 = (long)g_offset[e1 >> 16] + (e1 & 0xFFFF);
    float4 a = ((const float4*)(g_ybuf + r0 * DDIM))[threadIdx.x];
    float4 b = ((const float4*)(g_ybuf + r1 * DDIM))[threadIdx.x];
    ((float4*)(out + (size_t)t * DDIM))[threadIdx.x] =
        make_float4(a.x + b.x, a.y + b.y, a.z + b.z, a.w + b.w);
}

// ---------------- tf32 mma.sync GEMM: 128x64x16, 3-stage cp.async ----------
// G1: A = g_xbuf [rows,DDIM], Out = g_hbuf (gelu(.+b1))
// !G1: A = g_hbuf [rows,HDIM], Out = g_ybuf (wgt*(.+b2))
// Scratch buffers are referenced BY SYMBOL inside device code (never passed
// from host -- host-side &__device__ gives the host shadow address, which on
// GB300/ATS is silently dereferenceable and reads zeros).
template <int KDIM, int ODIM, bool G1>
__global__ void __launch_bounds__(256)
moe_gemm(const float* __restrict__ Bw, const float* __restrict__ bias) {
    constexpr int KT = KDIM / BK;
    const float* A = G1 ? g_xbuf : g_hbuf;
    float* Out = G1 ? g_hbuf : g_ybuf;

    const int e = blockIdx.z;
    const int m0 = blockIdx.y * BM;
    if (m0 >= g_cntp[e]) return;
    const int n0 = blockIdx.x * BN;
    const long arow0 = (long)g_offset[e] + m0;

    __shared__ float Asm[STG][BM][ASTR];
    __shared__ float Bsm[STG][BK][BSTR];

    const int tid = threadIdx.x;
    const int lane = tid & 31, wid = tid >> 5;
    const int wm = wid >> 1, wn = wid & 1;         // 4m x 2n warps, tile 32x32
    const int lr = lane >> 2, lc = lane & 3;

    const float* Ae = A + arow0 * KDIM;
    const float* Be = Bw + (size_t)e * KDIM * ODIM + n0;

    const int a_r0 = tid >> 2;            // + i*64
    const int a_k4 = (tid & 3) * 4;
    const int b_kr = tid >> 4;
    const int b_n4 = (tid & 15) * 4;

    float cr[2][4][4];
#pragma unroll
    for (int mi = 0; mi < 2; mi++)
#pragma unroll
        for (int ni = 0; ni < 4; ni++)
#pragma unroll
            for (int q = 0; q < 4; q++) cr[mi][ni][q] = 0.f;

    auto load_stage = [&](int kt, int buf) {
        const float* as = Ae + kt * BK;
        const float* bs = Be + (size_t)kt * BK * ODIM;
#pragma unroll
        for (int i = 0; i < 2; i++) {
            int r = a_r0 + i * 64;
            cpasync16(smem_u32(&Asm[buf][r][a_k4]), as + (size_t)r * KDIM + a_k4);
        }
        cpasync16(smem_u32(&Bsm[buf][b_kr][b_n4]), bs + (size_t)b_kr * ODIM + b_n4);
    };

#pragma unroll
    for (int s = 0; s < STG - 1; s++) {
        load_stage(s, s);
        asm volatile("cp.async.commit_group;" ::: "memory");
    }

#pragma unroll 1
    for (int kt = 0; kt < KT; kt++) {
        asm volatile("cp.async.wait_group 1;" ::: "memory");
        __syncthreads();

        int nk = kt + STG - 1;
        if (nk < KT) load_stage(nk, nk % STG);
        asm volatile("cp.async.commit_group;" ::: "memory");

        const int buf = kt % STG;
        const float* Ab = &Asm[buf][wm * 32 + lr][lc];
        const float* Bb = &Bsm[buf][lc][wn * 32 + lr];
#pragma unroll
        for (int kk = 0; kk < 2; kk++) {
            u32 af[2][4], bf[4][2];
#pragma unroll
            for (int mi = 0; mi < 2; mi++) {
                const float* ap = Ab + mi * (16 * ASTR) + kk * 8;
                af[mi][0] = f2tf(ap[0]);
                af[mi][1] = f2tf(ap[8 * ASTR]);
                af[mi][2] = f2tf(ap[4]);
                af[mi][3] = f2tf(ap[8 * ASTR + 4]);
            }
#pragma unroll
            for (int ni = 0; ni < 4; ni++) {
                const float* bp = Bb + kk * (8 * BSTR) + ni * 8;
                bf[ni][0] = f2tf(bp[0]);
                bf[ni][1] = f2tf(bp[4 * BSTR]);
            }
#pragma unroll
            for (int mi = 0; mi < 2; mi++)
#pragma unroll
                for (int ni = 0; ni < 4; ni++)
                    mmaop(cr[mi][ni], af[mi], bf[ni]);
        }
        __syncthreads();
    }

    // epilogue
    const float* bp = bias + (size_t)e * ODIM + n0 + wn * 32;
#pragma unroll
    for (int mi = 0; mi < 2; mi++) {
        int rlo = wm * 32 + mi * 16 + lr;
        int rhi = rlo + 8;
        float wlo = 1.f, whi = 1.f;
        if (!G1) {
            wlo = g_wgt[e * TMAX + m0 + rlo];
            whi = g_wgt[e * TMAX + m0 + rhi];
        }
        float* olo = Out + (arow0 + rlo) * (size_t)ODIM + n0 + wn * 32;
        float* ohi = Out + (arow0 + rhi) * (size_t)ODIM + n0 + wn * 32;
#pragma unroll
        for (int ni = 0; ni < 4; ni++) {
            int col = ni * 8 + 2 * lc;
            float b0v = bp[col], b1v = bp[col + 1];
            float v0 = cr[mi][ni][0] + b0v, v1 = cr[mi][ni][1] + b1v;
            float v2 = cr[mi][ni][2] + b0v, v3 = cr[mi][ni][3] + b1v;
            if (G1) {
                v0 = gelu_exact(v0); v1 = gelu_exact(v1);
                v2 = gelu_exact(v2); v3 = gelu_exact(v3);
            } else {
                v0 *= wlo; v1 *= wlo; v2 *= whi; v3 *= whi;
            }
            *(float2*)(olo + col) = make_float2(v0, v1);
            *(float2*)(ohi + col) = make_float2(v2, v3);
        }
    }
}

// ---------------- launch ----------------
extern "C" void kernel_launch(void* const* d_in, const int* in_sizes, int n_in,
                              void* d_out, int out_size) {
    const float* x      = (const float*)d_in[0];
    const float* gate_w = (const float*)d_in[1];
    const float* w1     = (const float*)d_in[2];
    const float* b1     = (const float*)d_in[3];
    const float* w2     = (const float*)d_in[4];
    const float* b2     = (const float*)d_in[5];
    float* out = (float*)d_out;
    const int T = in_sizes[0] / DDIM;

    zero_counts_kernel<<<1, 32>>>();
    router_kernel<<<(T + 7) / 8, 256>>>(x, gate_w, T);
    setup_kernel<<<1, 32>>>();
    gather_kernel<<<NSP, 256>>>(x);
    {
        dim3 g(HDIM / BN, TMAX / BM, ENUM);
        moe_gemm<DDIM, HDIM, true><<<g, 256>>>(w1, b1);
    }
    {
        dim3 g(DDIM / BN, TMAX / BM, ENUM);
        moe_gemm<HDIM, DDIM, false><<<g, 256>>>(w2, b2);
    }
    combine_kernel<<<T, 256>>>(out);
}